// round 3
// baseline (speedup 1.0000x reference)
#include <cuda_runtime.h>
#include <cuda_bf16.h>

// CropAndResize: image [8,256,64,64] f32 NCHW, boxes [1000,4] f32 (y1,x1,y2,x2),
// box_ind [1000] i32. Output [1000,256,14,14] f32, TF-style bilinear with
// extrapolation_value = 0 for out-of-bounds sample coordinates.
//
// R3: one block per (box, channel-pair). One thread per output pixel, lanes map
// to CONSECUTIVE pixels so each gather warp-LDG touches only ~2-3 input rows
// (compact L1 footprint). Coordinate math computed once per thread and reused
// for both channels (amortizes ALU, doubles in-flight loads).

namespace {
constexpr int C      = 256;
constexpr int H      = 64;
constexpr int W      = 64;
constexpr int CROP_H = 14;
constexpr int CROP_W = 14;
constexpr int PIX    = CROP_H * CROP_W;   // 196
constexpr int BLOCK  = 224;               // 7 full warps; lanes 196..223 idle
constexpr int CPB    = 2;                 // channels per block
}

__global__ __launch_bounds__(BLOCK)
void crop_resize_kernel(const float* __restrict__ img,
                        const float4* __restrict__ boxes,
                        const int* __restrict__ box_ind,
                        float* __restrict__ out)
{
    int p = threadIdx.x;
    if (p >= PIX) return;

    int blk = blockIdx.x;                 // blk = box * (C/CPB) + cpair
    int box = blk >> 7;                   // / 128
    int cp  = blk & 127;
    int c0  = cp * CPB;

    float4 bb = boxes[box];               // y1, x1, y2, x2  (uniform broadcast)
    int    b  = __ldg(box_ind + box);

    const float* __restrict__ plane0 = img + ((long)b * C + c0) * (H * W);
    const float* __restrict__ plane1 = plane0 + H * W;

    // Match reference rounding order: h_scale = ((y2-y1)*(H-1)) / (crop-1)
    float hs = ((bb.z - bb.x) * (float)(H - 1)) / (float)(CROP_H - 1);
    float ws = ((bb.w - bb.y) * (float)(W - 1)) / (float)(CROP_W - 1);
    float ybase = bb.x * (float)(H - 1);
    float xbase = bb.y * (float)(W - 1);

    int iy = p / CROP_W;
    int ix = p - iy * CROP_W;

    float in_y = ybase + (float)iy * hs;
    float in_x = xbase + (float)ix * ws;

    bool oob = (in_y < 0.0f) | (in_y > (float)(H - 1)) |
               (in_x < 0.0f) | (in_x > (float)(W - 1));

    float tf = floorf(in_y);
    float lf = floorf(in_x);
    float yl = in_y - tf;
    float xl = in_x - lf;

    int ti = min(max((int)tf, 0), H - 1);
    int bi = min(max((int)tf + 1, 0), H - 1);
    int li = min(max((int)lf, 0), W - 1);
    int ri = min(max((int)lf + 1, 0), W - 1);

    int otl = ti * W + li;
    int otr = ti * W + ri;
    int obl = bi * W + li;
    int obr = bi * W + ri;

    // Channel 0 gathers
    float tl0 = __ldg(plane0 + otl);
    float tr0 = __ldg(plane0 + otr);
    float bl0 = __ldg(plane0 + obl);
    float br0 = __ldg(plane0 + obr);
    // Channel 1 gathers (independent — overlap in flight)
    float tl1 = __ldg(plane1 + otl);
    float tr1 = __ldg(plane1 + otr);
    float bl1 = __ldg(plane1 + obl);
    float br1 = __ldg(plane1 + obr);

    float top0 = tl0 + (tr0 - tl0) * xl;
    float bot0 = bl0 + (br0 - bl0) * xl;
    float v0   = top0 + (bot0 - top0) * yl;

    float top1 = tl1 + (tr1 - tl1) * xl;
    float bot1 = bl1 + (br1 - bl1) * xl;
    float v1   = top1 + (bot1 - top1) * yl;

    long obase = ((long)box * C + c0) * PIX + p;
    out[obase]       = oob ? 0.0f : v0;
    out[obase + PIX] = oob ? 0.0f : v1;
}

extern "C" void kernel_launch(void* const* d_in, const int* in_sizes, int n_in,
                              void* d_out, int out_size)
{
    const float*  img     = (const float*)d_in[0];
    const float4* boxes   = (const float4*)d_in[1];
    const int*    box_ind = (const int*)d_in[2];
    float*        out     = (float*)d_out;

    int n_boxes = in_sizes[2];               // 1000
    int blocks  = n_boxes * (C / CPB);       // 128,000 blocks

    crop_resize_kernel<<<blocks, BLOCK>>>(img, boxes, box_ind, out);
}